// round 2
// baseline (speedup 1.0000x reference)
#include <cuda_runtime.h>
#include <cuda_bf16.h>

// ---------------------------------------------------------------------------
// HybridGNN: 2-layer bipartite mean-SAGE + edge classifier.
// CSR pull aggregation (no float atomics) + dual-input SIMT GEMMs using
// packed fp32 (fma.rn.f32x2) + factorized edge classifier.
// All scratch lives in __device__ globals referenced directly from device
// code (no cudaGetSymbolAddress). Edge dtype (int64 vs int32) detected at
// runtime on-device.
// ---------------------------------------------------------------------------

#define NN    50000
#define DIN   64
#define HH    128
#define EMAX  1000000
#define ETGT  500000

// ---------------- scratch ----------------
__device__ int g_stride;              // 2 if edges are int64 (as int32 pairs), 1 if int32
__device__ int g_deg[2][NN];          // [0]=merchant-dst (um), [1]=user-dst (mu)
__device__ int g_cur[2][NN];
__device__ int g_off[2][NN + 1];
__device__ int g_csr[2][EMAX];

__device__ float g_mean1_m[NN * DIN];
__device__ float g_mean1_u[NN * DIN];
__device__ float g_h_m[NN * HH];
__device__ float g_h_u[NN * HH];
__device__ float g_mean2_m[NN * HH];
__device__ float g_mean2_u[NN * HH];
__device__ float g_z_m[NN * HH];
__device__ float g_z_u[NN * HH];
__device__ float g_Pu[NN * HH];
__device__ float g_Pm[NN * HH];

// transposed weights, layout [Ktot][128]
__device__ float g_wt1_um[128 * 128];
__device__ float g_wt1_mu[128 * 128];
__device__ float g_wt2_um[256 * 128];
__device__ float g_wt2_mu[256 * 128];
__device__ float g_wtc_u[128 * 128];
__device__ float g_wtc_m[128 * 128];

// id -> device-global buffer (device-side address-of; no host symbol lookup)
__device__ __forceinline__ float* gbuf(int id) {
    switch (id) {
        case 0:  return g_mean1_m;  case 1:  return g_mean1_u;
        case 2:  return g_h_m;      case 3:  return g_h_u;
        case 4:  return g_mean2_m;  case 5:  return g_mean2_u;
        case 6:  return g_z_m;      case 7:  return g_z_u;
        case 8:  return g_Pu;       case 9:  return g_Pm;
        case 10: return g_wt1_um;   case 11: return g_wt1_mu;
        case 12: return g_wt2_um;   case 13: return g_wt2_mu;
        case 14: return g_wtc_u;    case 15: return g_wtc_m;
    }
    return nullptr;
}

// ---------------- dtype detect -----------------------------------------------
// int64 edges (values < 2^31, nonnegative) => every odd int32 word is 0.
__global__ void detect_kernel(const int* __restrict__ e) {
    int lane = threadIdx.x;
    int v = 0;
#pragma unroll
    for (int i = 0; i < 4; ++i) v |= e[2 * (lane + 32 * i) + 1];
    unsigned nz = __ballot_sync(0xffffffffu, v != 0);
    if (lane == 0) g_stride = (nz == 0u) ? 2 : 1;
}

// ---------------- CSR build ---------------------------------------------------
__global__ void zero_counts_kernel() {
    int i = blockIdx.x * blockDim.x + threadIdx.x;
    if (i < NN) {
        g_deg[0][i] = 0; g_deg[1][i] = 0;
        g_cur[0][i] = 0; g_cur[1][i] = 0;
    }
}

template <int W>
__global__ void count_kernel(const int* __restrict__ e, int E) {
    int i = blockIdx.x * blockDim.x + threadIdx.x;
    if (i >= E) return;
    int st = g_stride;
    int col = e[st * (E + i)];
    atomicAdd(&g_deg[W][col], 1);
}

template <int W>
__global__ void scan_kernel() {
    __shared__ int s[1024];
    int t = threadIdx.x;
    const int n = NN;
    int per = (n + 1023) / 1024;
    int start = t * per;
    int end = start + per; if (end > n) end = n; if (start > n) start = n;
    int sum = 0;
    for (int i = start; i < end; ++i) sum += g_deg[W][i];
    s[t] = sum;
    __syncthreads();
    for (int d = 1; d < 1024; d <<= 1) {
        int v = (t >= d) ? s[t - d] : 0;
        __syncthreads();
        s[t] += v;
        __syncthreads();
    }
    int run = (t == 0) ? 0 : s[t - 1];
    for (int i = start; i < end; ++i) { g_off[W][i] = run; run += g_deg[W][i]; }
    if (t == 1023) g_off[W][n] = s[1023];
}

template <int W>
__global__ void scatter_kernel(const int* __restrict__ e, int E) {
    int i = blockIdx.x * blockDim.x + threadIdx.x;
    if (i >= E) return;
    int st = g_stride;
    int row = e[st * i];
    int col = e[st * (E + i)];
    int p = g_off[W][col] + atomicAdd(&g_cur[W][col], 1);
    g_csr[W][p] = row;
}

// ---------------- weight transpose --------------------------------------------
// dst[dst_off + k*128 + n] = src[n*ld + src_off + k]
__global__ void transpose_w_kernel(const float* __restrict__ src, int ld, int src_off,
                                   int dst_id, int dst_off, int K) {
    int idx = blockIdx.x * blockDim.x + threadIdx.x;
    if (idx >= K * 128) return;
    int nn = idx & 127;
    int k  = idx >> 7;
    gbuf(dst_id)[dst_off + idx] = src[nn * ld + src_off + k];
}

// ---------------- pull-based mean aggregation ----------------------------------
// one warp per destination node; neighbor rows accumulated in registers.
template <int D, int W>
__global__ void pull_mean_kernel(const float* __restrict__ xext, int xid, int out_id) {
    int w    = (blockIdx.x * blockDim.x + threadIdx.x) >> 5;
    int lane = threadIdx.x & 31;
    if (w >= NN) return;
    const float* xsrc = xext ? xext : gbuf(xid);
    float* mean_out = gbuf(out_id);
    int s0 = g_off[W][w], s1 = g_off[W][w + 1];
    float inv = 1.0f / fmaxf((float)(s1 - s0), 1.0f);
    if (D == 128) {
        const float4* xv = (const float4*)xsrc;
        float4 acc = make_float4(0.f, 0.f, 0.f, 0.f);
        for (int j = s0; j < s1; ++j) {
            int s = g_csr[W][j];
            float4 v = __ldg(&xv[s * 32 + lane]);
            acc.x += v.x; acc.y += v.y; acc.z += v.z; acc.w += v.w;
        }
        acc.x *= inv; acc.y *= inv; acc.z *= inv; acc.w *= inv;
        ((float4*)mean_out)[w * 32 + lane] = acc;
    } else {  // D == 64
        const float2* xv = (const float2*)xsrc;
        float2 acc = make_float2(0.f, 0.f);
        for (int j = s0; j < s1; ++j) {
            int s = g_csr[W][j];
            float2 v = __ldg(&xv[s * 32 + lane]);
            acc.x += v.x; acc.y += v.y;
        }
        acc.x *= inv; acc.y *= inv;
        ((float2*)mean_out)[w * 32 + lane] = acc;
    }
}

// ---------------- dual-input GEMM (packed fp32 FFMA2) ---------------------------
// out[NN x 128] = act( [A1 | A2] @ Wt + bias ), Wt pre-transposed [Ktot][128].
__device__ __forceinline__ void ffma2(unsigned long long& d,
                                      unsigned long long a, unsigned long long b) {
    asm("fma.rn.f32x2 %0, %1, %2, %0;" : "+l"(d) : "l"(a), "l"(b));
}

__global__ __launch_bounds__(256)
void gemm_dual_kernel(int a1_id, const float* __restrict__ a2_ext, int a2_id,
                      int K1, int K2, int wt_id,
                      const float* __restrict__ bias,
                      int out_id, int doRelu) {
    __shared__ float2 As[16][129];   // A values duplicated {v,v}, padded
    __shared__ float  Bs[16][128];
    const int t  = threadIdx.x;
    const int tx = t & 15;           // column group
    const int ty = t >> 4;           // row group
    const int r0 = blockIdx.x * 128;
    const int n = NN;

    const float* A1 = gbuf(a1_id);
    const float* A2 = a2_ext ? a2_ext : (a2_id >= 0 ? gbuf(a2_id) : nullptr);
    const float* Wt = gbuf(wt_id);
    float* out = gbuf(out_id);

    unsigned long long acc[8][4];
#pragma unroll
    for (int i = 0; i < 8; ++i)
#pragma unroll
        for (int p = 0; p < 4; ++p) acc[i][p] = 0ull;

    const int Ktot = K1 + K2;
    for (int k0 = 0; k0 < Ktot; k0 += 16) {
        const float* A; int K, kb;
        if (k0 < K1) { A = A1; K = K1; kb = k0; }
        else         { A = A2; K = K2; kb = k0 - K1; }
#pragma unroll
        for (int i = 0; i < 8; ++i) {
            int idx = t + 256 * i;             // 2048 elements
            int k = idx & 15, m = idx >> 4;
            int row = r0 + m;
            float v = (row < n) ? A[row * K + kb + k] : 0.f;
            As[k][m] = make_float2(v, v);
        }
#pragma unroll
        for (int i = 0; i < 8; ++i) {
            int idx = t + 256 * i;             // 2048 elements
            int nn = idx & 127, k = idx >> 7;
            Bs[k][nn] = Wt[(k0 + k) * 128 + nn];
        }
        __syncthreads();
#pragma unroll
        for (int k = 0; k < 16; ++k) {
            unsigned long long a[8], b[4];
#pragma unroll
            for (int i = 0; i < 8; ++i)
                a[i] = *(const unsigned long long*)&As[k][ty * 8 + i];
#pragma unroll
            for (int p = 0; p < 4; ++p)
                b[p] = *(const unsigned long long*)&Bs[k][2 * tx + 32 * p];
#pragma unroll
            for (int i = 0; i < 8; ++i)
#pragma unroll
                for (int p = 0; p < 4; ++p) ffma2(acc[i][p], a[i], b[p]);
        }
        __syncthreads();
    }

    float2 bb[4];
#pragma unroll
    for (int p = 0; p < 4; ++p) {
        int c = 2 * tx + 32 * p;
        bb[p] = bias ? *(const float2*)&bias[c] : make_float2(0.f, 0.f);
    }
#pragma unroll
    for (int i = 0; i < 8; ++i) {
        int row = r0 + ty * 8 + i;
        if (row >= n) continue;
#pragma unroll
        for (int p = 0; p < 4; ++p) {
            float2 v = *(float2*)&acc[i][p];
            v.x += bb[p].x; v.y += bb[p].y;
            if (doRelu) { v.x = fmaxf(v.x, 0.f); v.y = fmaxf(v.y, 0.f); }
            *(float2*)&out[row * 128 + 2 * tx + 32 * p] = v;
        }
    }
}

// ---------------- edge classifier ------------------------------------------------
// out[e] = dot( relu(Pu[row] + Pm[col]), Wc2 ) + bc2   (bc1 folded into Pu)
__global__ void edge_cls_kernel(const int* __restrict__ tei, int Et,
                                const float* __restrict__ Wc2,
                                const float* __restrict__ bc2,
                                float* __restrict__ out) {
    int w    = (blockIdx.x * blockDim.x + threadIdx.x) >> 5;
    int lane = threadIdx.x & 31;
    if (w >= Et) return;
    int st = g_stride;
    int ru = tei[st * w];             // user idx
    int rm = tei[st * (Et + w)];      // merchant idx
    float4 u  = __ldg(&((const float4*)g_Pu)[ru * 32 + lane]);
    float4 m  = __ldg(&((const float4*)g_Pm)[rm * 32 + lane]);
    float4 wv = __ldg(&((const float4*)Wc2)[lane]);
    float a = fmaxf(u.x + m.x, 0.f) * wv.x
            + fmaxf(u.y + m.y, 0.f) * wv.y
            + fmaxf(u.z + m.z, 0.f) * wv.z
            + fmaxf(u.w + m.w, 0.f) * wv.w;
#pragma unroll
    for (int o = 16; o; o >>= 1) a += __shfl_xor_sync(0xffffffffu, a, o);
    if (lane == 0) out[w] = a + bc2[0];
}

// ---------------- host launcher ---------------------------------------------------
extern "C" void kernel_launch(void* const* d_in, const int* in_sizes, int n_in,
                              void* d_out, int out_size) {
    const float* x_user  = (const float*)d_in[0];
    const float* x_merch = (const float*)d_in[1];
    const int*   e_um    = (const int*)d_in[2];
    const int*   e_mu    = (const int*)d_in[3];
    const int*   tei     = (const int*)d_in[4];
    const float* W1_um_l = (const float*)d_in[5];
    const float* b1_um_l = (const float*)d_in[6];
    const float* W1_um_r = (const float*)d_in[7];
    const float* W1_mu_l = (const float*)d_in[8];
    const float* b1_mu_l = (const float*)d_in[9];
    const float* W1_mu_r = (const float*)d_in[10];
    const float* W2_um_l = (const float*)d_in[11];
    const float* b2_um_l = (const float*)d_in[12];
    const float* W2_um_r = (const float*)d_in[13];
    const float* W2_mu_l = (const float*)d_in[14];
    const float* b2_mu_l = (const float*)d_in[15];
    const float* W2_mu_r = (const float*)d_in[16];
    const float* Wc1     = (const float*)d_in[17];
    const float* bc1     = (const float*)d_in[18];
    const float* Wc2     = (const float*)d_in[19];
    const float* bc2     = (const float*)d_in[20];

    const int E  = EMAX;   // shapes fixed by problem definition
    const int Et = ETGT;
    float* out = (float*)d_out;

    // 0) detect edge dtype + zero degree/cursor arrays
    detect_kernel<<<1, 32>>>(e_um);
    zero_counts_kernel<<<(NN + 255) / 256, 256>>>();

    // 1) weight transposes (tiny)
    auto T = [](const float* s, int ld, int soff, int did, int doff, int K) {
        transpose_w_kernel<<<(K * 128 + 255) / 256, 256>>>(s, ld, soff, did, doff, K);
    };
    T(W1_um_l, 64, 0, 10, 0, 64);      T(W1_um_r, 64, 0, 10, 64 * 128, 64);
    T(W1_mu_l, 64, 0, 11, 0, 64);      T(W1_mu_r, 64, 0, 11, 64 * 128, 64);
    T(W2_um_l, 128, 0, 12, 0, 128);    T(W2_um_r, 128, 0, 12, 128 * 128, 128);
    T(W2_mu_l, 128, 0, 13, 0, 128);    T(W2_mu_r, 128, 0, 13, 128 * 128, 128);
    T(Wc1, 256, 0, 14, 0, 128);        T(Wc1, 256, 128, 15, 0, 128);

    // 2) CSR build (per edge type)
    const int EB = (E + 255) / 256;
    count_kernel<0><<<EB, 256>>>(e_um, E);
    count_kernel<1><<<EB, 256>>>(e_mu, E);
    scan_kernel<0><<<1, 1024>>>();
    scan_kernel<1><<<1, 1024>>>();
    scatter_kernel<0><<<EB, 256>>>(e_um, E);
    scatter_kernel<1><<<EB, 256>>>(e_mu, E);

    const int PB = (NN * 32 + 255) / 256;  // 1 warp per dst node
    const int GB = (NN + 127) / 128;       // GEMM row blocks

    // 3) layer 1: h_m = relu(sage(x_user->merchant)), h_u = relu(sage(x_merch->user))
    pull_mean_kernel<64, 0><<<PB, 256>>>(x_user,  -1, 0);
    pull_mean_kernel<64, 1><<<PB, 256>>>(x_merch, -1, 1);
    gemm_dual_kernel<<<GB, 256>>>(0, x_merch, -1, 64, 64, 10, b1_um_l, 2, 1);
    gemm_dual_kernel<<<GB, 256>>>(1, x_user,  -1, 64, 64, 11, b1_mu_l, 3, 1);

    // 4) layer 2 (no relu)
    pull_mean_kernel<128, 0><<<PB, 256>>>(nullptr, 3, 4);  // from h_u
    pull_mean_kernel<128, 1><<<PB, 256>>>(nullptr, 2, 5);  // from h_m
    gemm_dual_kernel<<<GB, 256>>>(4, nullptr, 2, 128, 128, 12, b2_um_l, 6, 0);
    gemm_dual_kernel<<<GB, 256>>>(5, nullptr, 3, 128, 128, 13, b2_mu_l, 7, 0);

    // 5) classifier projections (bc1 folded into Pu)
    gemm_dual_kernel<<<GB, 256>>>(7, nullptr, -1, 128, 0, 14, bc1, 8, 0);
    gemm_dual_kernel<<<GB, 256>>>(6, nullptr, -1, 128, 0, 15, nullptr, 9, 0);

    // 6) per-edge output
    edge_cls_kernel<<<(Et * 32 + 255) / 256, 256>>>(tei, Et, Wc2, bc2, out);
}

// round 3
// speedup vs baseline: 1.1679x; 1.1679x over previous
#include <cuda_runtime.h>
#include <cuda_bf16.h>

// ---------------------------------------------------------------------------
// HybridGNN: 2-layer bipartite mean-SAGE + edge classifier.
// R2: GEMM inner loop rebuilt around LDS.128 (84% FFMA2 issue share), BK=32,
// GEMM pairs merged into single launches (wave-quantization fix), all tiny
// setup work fused into one kernel. 10 launches total.
// ---------------------------------------------------------------------------

#define NN    50000
#define DIN   64
#define HH    128
#define EMAX  1000000
#define ETGT  500000

// ---------------- scratch ----------------
__device__ int g_stride;              // 2 if edges are int64 (int32 pairs), 1 if int32
__device__ int g_deg[2][NN];          // [0]=merchant-dst (um), [1]=user-dst (mu)
__device__ int g_cur[2][NN];
__device__ int g_off[2][NN + 1];
__device__ int g_csr[2][EMAX];

__device__ float g_mean1_m[NN * DIN];
__device__ float g_mean1_u[NN * DIN];
__device__ float g_h_m[NN * HH];
__device__ float g_h_u[NN * HH];
__device__ float g_mean2_m[NN * HH];
__device__ float g_mean2_u[NN * HH];
__device__ float g_z_m[NN * HH];
__device__ float g_z_u[NN * HH];
__device__ float g_Pu[NN * HH];
__device__ float g_Pm[NN * HH];

// transposed weights, layout [Ktot][128]
__device__ float g_wt1_um[128 * 128];
__device__ float g_wt1_mu[128 * 128];
__device__ float g_wt2_um[256 * 128];
__device__ float g_wt2_mu[256 * 128];
__device__ float g_wtc_u[128 * 128];
__device__ float g_wtc_m[128 * 128];

__device__ __forceinline__ float* gbuf(int id) {
    switch (id) {
        case 0:  return g_mean1_m;  case 1:  return g_mean1_u;
        case 2:  return g_h_m;      case 3:  return g_h_u;
        case 4:  return g_mean2_m;  case 5:  return g_mean2_u;
        case 6:  return g_z_m;      case 7:  return g_z_u;
        case 8:  return g_Pu;       case 9:  return g_Pm;
        case 10: return g_wt1_um;   case 11: return g_wt1_mu;
        case 12: return g_wt2_um;   case 13: return g_wt2_mu;
        case 14: return g_wtc_u;    case 15: return g_wtc_m;
    }
    return nullptr;
}

// ---------------- fused setup: weight transpose + zero counters + dtype detect
struct SetupArgs {
    const float* src[10];
    int ld[10], soff[10], did[10];
    int start[11];
    const int* e_detect;
};

__global__ void setup_kernel(SetupArgs a) {
    int idx = blockIdx.x * blockDim.x + threadIdx.x;
    if (idx < NN) {
        g_deg[0][idx] = 0; g_deg[1][idx] = 0;
        g_cur[0][idx] = 0; g_cur[1][idx] = 0;
    }
    if (blockIdx.x == 0 && threadIdx.x < 32) {
        int lane = threadIdx.x, v = 0;
#pragma unroll
        for (int i = 0; i < 4; ++i) v |= a.e_detect[2 * (lane + 32 * i) + 1];
        unsigned nz = __ballot_sync(0xffffffffu, v != 0);
        if (lane == 0) g_stride = (nz == 0u) ? 2 : 1;
    }
    if (idx >= a.start[10]) return;
    int s = 0;
    while (idx >= a.start[s + 1]) ++s;
    int rel = idx - a.start[s];
    int nn = rel & 127, k = rel >> 7;
    gbuf(a.did[s])[rel] = a.src[s][nn * a.ld[s] + a.soff[s] + k];
}

// dst offsets folded by giving wt2 halves separate "did" handling:
// we instead write via did + doff encoded: use separate segments writing into
// the same buffer at doff. Simplify: gbuf(did)[doff + rel]. Keep doff array.
struct SetupArgs2 {
    const float* src[10];
    int ld[10], soff[10], did[10], doff[10];
    int start[11];
    const int* e_detect;
};

__global__ void setup2_kernel(SetupArgs2 a) {
    int idx = blockIdx.x * blockDim.x + threadIdx.x;
    if (idx < NN) {
        g_deg[0][idx] = 0; g_deg[1][idx] = 0;
        g_cur[0][idx] = 0; g_cur[1][idx] = 0;
    }
    if (blockIdx.x == 0 && threadIdx.x < 32) {
        int lane = threadIdx.x, v = 0;
#pragma unroll
        for (int i = 0; i < 4; ++i) v |= a.e_detect[2 * (lane + 32 * i) + 1];
        unsigned nz = __ballot_sync(0xffffffffu, v != 0);
        if (lane == 0) g_stride = (nz == 0u) ? 2 : 1;
    }
    if (idx >= a.start[10]) return;
    int s = 0;
    while (idx >= a.start[s + 1]) ++s;
    int rel = idx - a.start[s];
    int nn = rel & 127, k = rel >> 7;
    gbuf(a.did[s])[a.doff[s] + rel] = a.src[s][nn * a.ld[s] + a.soff[s] + k];
}

// ---------------- CSR build ----------------
__global__ void count_both_kernel(const int* __restrict__ e0,
                                  const int* __restrict__ e1, int E) {
    int i = blockIdx.x * blockDim.x + threadIdx.x;
    if (i >= E) return;
    int W = blockIdx.y;
    const int* e = W ? e1 : e0;
    int st = g_stride;
    atomicAdd(&g_deg[W][e[st * (E + i)]], 1);
}

__global__ void scan_both_kernel() {
    __shared__ int s[1024];
    int W = blockIdx.x;
    int t = threadIdx.x;
    const int n = NN;
    int per = (n + 1023) / 1024;
    int start = t * per;
    int end = start + per; if (end > n) end = n; if (start > n) start = n;
    int sum = 0;
    for (int i = start; i < end; ++i) sum += g_deg[W][i];
    s[t] = sum;
    __syncthreads();
    for (int d = 1; d < 1024; d <<= 1) {
        int v = (t >= d) ? s[t - d] : 0;
        __syncthreads();
        s[t] += v;
        __syncthreads();
    }
    int run = (t == 0) ? 0 : s[t - 1];
    for (int i = start; i < end; ++i) { g_off[W][i] = run; run += g_deg[W][i]; }
    if (t == 1023) g_off[W][n] = s[1023];
}

__global__ void scatter_both_kernel(const int* __restrict__ e0,
                                    const int* __restrict__ e1, int E) {
    int i = blockIdx.x * blockDim.x + threadIdx.x;
    if (i >= E) return;
    int W = blockIdx.y;
    const int* e = W ? e1 : e0;
    int st = g_stride;
    int row = e[st * i];
    int col = e[st * (E + i)];
    int p = g_off[W][col] + atomicAdd(&g_cur[W][col], 1);
    g_csr[W][p] = row;
}

// ---------------- pull-based mean aggregation (both edge types in one launch)
template <int D>
__global__ void pull_pair_kernel(const float* __restrict__ x0, int x0_id, int o0,
                                 const float* __restrict__ x1, int x1_id, int o1) {
    int W = blockIdx.y;
    int w    = (blockIdx.x * blockDim.x + threadIdx.x) >> 5;
    int lane = threadIdx.x & 31;
    if (w >= NN) return;
    const float* xsrc = W ? (x1 ? x1 : gbuf(x1_id)) : (x0 ? x0 : gbuf(x0_id));
    float* mean_out = gbuf(W ? o1 : o0);
    const int* __restrict__ csr = g_csr[W];
    int s0 = g_off[W][w], s1 = g_off[W][w + 1];
    float inv = 1.0f / fmaxf((float)(s1 - s0), 1.0f);
    if (D == 128) {
        const float4* xv = (const float4*)xsrc;
        float4 acc = make_float4(0.f, 0.f, 0.f, 0.f);
        for (int j = s0; j < s1; ++j) {
            int s = csr[j];
            float4 v = __ldg(&xv[s * 32 + lane]);
            acc.x += v.x; acc.y += v.y; acc.z += v.z; acc.w += v.w;
        }
        acc.x *= inv; acc.y *= inv; acc.z *= inv; acc.w *= inv;
        ((float4*)mean_out)[w * 32 + lane] = acc;
    } else {  // D == 64
        const float2* xv = (const float2*)xsrc;
        float2 acc = make_float2(0.f, 0.f);
        for (int j = s0; j < s1; ++j) {
            int s = csr[j];
            float2 v = __ldg(&xv[s * 32 + lane]);
            acc.x += v.x; acc.y += v.y;
        }
        acc.x *= inv; acc.y *= inv;
        ((float2*)mean_out)[w * 32 + lane] = acc;
    }
}

// ---------------- dual-input paired GEMM (packed fp32 FFMA2, LDS.128) ---------
__device__ __forceinline__ void ffma2(unsigned long long& d,
                                      unsigned long long a, unsigned long long b) {
    asm("fma.rn.f32x2 %0, %1, %2, %0;" : "+l"(d) : "l"(a), "l"(b));
}

struct GemmPairArgs {
    const float* a2_ext[2];
    const float* bias[2];
    int a1_id[2], a2_id[2], wt_id[2], out_id[2];
    int K1, K2, doRelu;
};

__global__ __launch_bounds__(256)
void gemm_pair_kernel(GemmPairArgs ga) {
    __shared__ float2 As[32][128];   // A values duplicated {v,v}; 32KB
    __shared__ float  Bs[32][128];   // 16KB
    const int g  = blockIdx.y;
    const int t  = threadIdx.x;
    const int tx = t & 15;
    const int ty = t >> 4;
    const int r0 = blockIdx.x * 128;

    const float* A1 = gbuf(ga.a1_id[g]);
    const float* A2 = ga.a2_ext[g] ? ga.a2_ext[g]
                                   : (ga.a2_id[g] >= 0 ? gbuf(ga.a2_id[g]) : nullptr);
    const float* Wt = gbuf(ga.wt_id[g]);
    const float* bias = ga.bias[g];
    float* out = gbuf(ga.out_id[g]);
    const int K1 = ga.K1, Ktot = ga.K1 + ga.K2;

    unsigned long long acc[8][4];
#pragma unroll
    for (int i = 0; i < 8; ++i)
#pragma unroll
        for (int p = 0; p < 4; ++p) acc[i][p] = 0ull;

    const int mA   = t >> 1;          // A-load row within tile
    const int kkA  = (t & 1) * 16;    // A-load k sub-chunk
    const int rowA = r0 + mA;

    for (int k0 = 0; k0 < Ktot; k0 += 32) {
        const float* A; int K, kb;
        if (k0 < K1) { A = A1; K = K1; kb = k0; }
        else         { A = A2; K = ga.K2; kb = k0 - K1; }
        const float* srcA = A + (size_t)rowA * K + kb + kkA;
#pragma unroll
        for (int j = 0; j < 4; ++j) {
            float4 v = make_float4(0.f, 0.f, 0.f, 0.f);
            if (rowA < NN) v = *(const float4*)(srcA + 4 * j);
            As[kkA + 4 * j + 0][mA] = make_float2(v.x, v.x);
            As[kkA + 4 * j + 1][mA] = make_float2(v.y, v.y);
            As[kkA + 4 * j + 2][mA] = make_float2(v.z, v.z);
            As[kkA + 4 * j + 3][mA] = make_float2(v.w, v.w);
        }
#pragma unroll
        for (int j = 0; j < 4; ++j) {
            int f = t + 256 * j;
            int k = f >> 5, c = (f & 31) << 2;
            *(float4*)&Bs[k][c] = __ldg((const float4*)&Wt[(k0 + k) * 128 + c]);
        }
        __syncthreads();
#pragma unroll
        for (int k = 0; k < 32; ++k) {
            unsigned long long av[8], bv[4];
            ulonglong2 a0 = *(const ulonglong2*)&As[k][ty * 8 + 0];
            ulonglong2 a1 = *(const ulonglong2*)&As[k][ty * 8 + 2];
            ulonglong2 a2 = *(const ulonglong2*)&As[k][ty * 8 + 4];
            ulonglong2 a3 = *(const ulonglong2*)&As[k][ty * 8 + 6];
            av[0] = a0.x; av[1] = a0.y; av[2] = a1.x; av[3] = a1.y;
            av[4] = a2.x; av[5] = a2.y; av[6] = a3.x; av[7] = a3.y;
            const float2* bs2 = (const float2*)Bs[k];
            ulonglong2 b0 = *(const ulonglong2*)&bs2[2 * tx];        // cols 4tx..4tx+3
            ulonglong2 b1 = *(const ulonglong2*)&bs2[32 + 2 * tx];   // cols 64+4tx..
            bv[0] = b0.x; bv[1] = b0.y; bv[2] = b1.x; bv[3] = b1.y;
#pragma unroll
            for (int i = 0; i < 8; ++i) {
                ffma2(acc[i][0], av[i], bv[0]);
                ffma2(acc[i][1], av[i], bv[1]);
                ffma2(acc[i][2], av[i], bv[2]);
                ffma2(acc[i][3], av[i], bv[3]);
            }
        }
        __syncthreads();
    }

    float4 bb0 = make_float4(0.f, 0.f, 0.f, 0.f), bb1 = bb0;
    if (bias) {
        bb0 = *(const float4*)&bias[4 * tx];
        bb1 = *(const float4*)&bias[64 + 4 * tx];
    }
#pragma unroll
    for (int i = 0; i < 8; ++i) {
        int row = r0 + ty * 8 + i;
        if (row >= NN) continue;
        float2 v0 = *(float2*)&acc[i][0], v1 = *(float2*)&acc[i][1];
        float2 v2 = *(float2*)&acc[i][2], v3 = *(float2*)&acc[i][3];
        float4 o0 = make_float4(v0.x + bb0.x, v0.y + bb0.y, v1.x + bb0.z, v1.y + bb0.w);
        float4 o1 = make_float4(v2.x + bb1.x, v2.y + bb1.y, v3.x + bb1.z, v3.y + bb1.w);
        if (ga.doRelu) {
            o0.x = fmaxf(o0.x, 0.f); o0.y = fmaxf(o0.y, 0.f);
            o0.z = fmaxf(o0.z, 0.f); o0.w = fmaxf(o0.w, 0.f);
            o1.x = fmaxf(o1.x, 0.f); o1.y = fmaxf(o1.y, 0.f);
            o1.z = fmaxf(o1.z, 0.f); o1.w = fmaxf(o1.w, 0.f);
        }
        *(float4*)&out[(size_t)row * 128 + 4 * tx] = o0;
        *(float4*)&out[(size_t)row * 128 + 64 + 4 * tx] = o1;
    }
}

// ---------------- edge classifier ----------------
__global__ void edge_cls_kernel(const int* __restrict__ tei, int Et,
                                const float* __restrict__ Wc2,
                                const float* __restrict__ bc2,
                                float* __restrict__ out) {
    int w    = (blockIdx.x * blockDim.x + threadIdx.x) >> 5;
    int lane = threadIdx.x & 31;
    if (w >= Et) return;
    int st = g_stride;
    int ru = tei[st * w];             // user idx
    int rm = tei[st * (Et + w)];      // merchant idx
    float4 u  = __ldg(&((const float4*)g_Pu)[ru * 32 + lane]);
    float4 m  = __ldg(&((const float4*)g_Pm)[rm * 32 + lane]);
    float4 wv = __ldg(&((const float4*)Wc2)[lane]);
    float a = fmaxf(u.x + m.x, 0.f) * wv.x
            + fmaxf(u.y + m.y, 0.f) * wv.y
            + fmaxf(u.z + m.z, 0.f) * wv.z
            + fmaxf(u.w + m.w, 0.f) * wv.w;
#pragma unroll
    for (int o = 16; o; o >>= 1) a += __shfl_xor_sync(0xffffffffu, a, o);
    if (lane == 0) out[w] = a + bc2[0];
}

// ---------------- host launcher ----------------
extern "C" void kernel_launch(void* const* d_in, const int* in_sizes, int n_in,
                              void* d_out, int out_size) {
    const float* x_user  = (const float*)d_in[0];
    const float* x_merch = (const float*)d_in[1];
    const int*   e_um    = (const int*)d_in[2];
    const int*   e_mu    = (const int*)d_in[3];
    const int*   tei     = (const int*)d_in[4];
    const float* W1_um_l = (const float*)d_in[5];
    const float* b1_um_l = (const float*)d_in[6];
    const float* W1_um_r = (const float*)d_in[7];
    const float* W1_mu_l = (const float*)d_in[8];
    const float* b1_mu_l = (const float*)d_in[9];
    const float* W1_mu_r = (const float*)d_in[10];
    const float* W2_um_l = (const float*)d_in[11];
    const float* b2_um_l = (const float*)d_in[12];
    const float* W2_um_r = (const float*)d_in[13];
    const float* W2_mu_l = (const float*)d_in[14];
    const float* b2_mu_l = (const float*)d_in[15];
    const float* W2_mu_r = (const float*)d_in[16];
    const float* Wc1     = (const float*)d_in[17];
    const float* bc1     = (const float*)d_in[18];
    const float* Wc2     = (const float*)d_in[19];
    const float* bc2     = (const float*)d_in[20];

    const int E  = EMAX;
    const int Et = ETGT;
    float* out = (float*)d_out;

    // 1) fused setup: transposes + zero counters + dtype detect
    SetupArgs2 sa;
    const float* srcs[10] = {W1_um_l, W1_um_r, W1_mu_l, W1_mu_r,
                             W2_um_l, W2_um_r, W2_mu_l, W2_mu_r, Wc1, Wc1};
    int lds[10]  = {64, 64, 64, 64, 128, 128, 128, 128, 256, 256};
    int soffs[10] = {0, 0, 0, 0, 0, 0, 0, 0, 0, 128};
    int dids[10]  = {10, 10, 11, 11, 12, 12, 13, 13, 14, 15};
    int doffs[10] = {0, 64 * 128, 0, 64 * 128, 0, 128 * 128, 0, 128 * 128, 0, 0};
    int Ks[10]    = {64, 64, 64, 64, 128, 128, 128, 128, 128, 128};
    int run = 0;
    for (int i = 0; i < 10; ++i) {
        sa.src[i] = srcs[i]; sa.ld[i] = lds[i]; sa.soff[i] = soffs[i];
        sa.did[i] = dids[i]; sa.doff[i] = doffs[i];
        sa.start[i] = run; run += Ks[i] * 128;
    }
    sa.start[10] = run;   // 131072
    sa.e_detect = e_um;
    setup2_kernel<<<(run + 255) / 256, 256>>>(sa);

    // 2) CSR build (both edge types per launch)
    const int EB = (E + 255) / 256;
    count_both_kernel<<<dim3(EB, 2), 256>>>(e_um, e_mu, E);
    scan_both_kernel<<<2, 1024>>>();
    scatter_both_kernel<<<dim3(EB, 2), 256>>>(e_um, e_mu, E);

    const int PB = (NN * 32 + 255) / 256;
    const int GB = (NN + 127) / 128;

    // 3) layer 1
    pull_pair_kernel<64><<<dim3(PB, 2), 256>>>(x_user, -1, 0, x_merch, -1, 1);
    GemmPairArgs g1;
    g1.a1_id[0] = 0; g1.a2_ext[0] = x_merch; g1.a2_id[0] = -1;
    g1.wt_id[0] = 10; g1.bias[0] = b1_um_l; g1.out_id[0] = 2;
    g1.a1_id[1] = 1; g1.a2_ext[1] = x_user;  g1.a2_id[1] = -1;
    g1.wt_id[1] = 11; g1.bias[1] = b1_mu_l; g1.out_id[1] = 3;
    g1.K1 = 64; g1.K2 = 64; g1.doRelu = 1;
    gemm_pair_kernel<<<dim3(GB, 2), 256>>>(g1);

    // 4) layer 2 (no relu)
    pull_pair_kernel<128><<<dim3(PB, 2), 256>>>(nullptr, 3, 4, nullptr, 2, 5);
    GemmPairArgs g2;
    g2.a1_id[0] = 4; g2.a2_ext[0] = nullptr; g2.a2_id[0] = 2;
    g2.wt_id[0] = 12; g2.bias[0] = b2_um_l; g2.out_id[0] = 6;
    g2.a1_id[1] = 5; g2.a2_ext[1] = nullptr; g2.a2_id[1] = 3;
    g2.wt_id[1] = 13; g2.bias[1] = b2_mu_l; g2.out_id[1] = 7;
    g2.K1 = 128; g2.K2 = 128; g2.doRelu = 0;
    gemm_pair_kernel<<<dim3(GB, 2), 256>>>(g2);

    // 5) classifier projections (bc1 folded into Pu)
    GemmPairArgs gc;
    gc.a1_id[0] = 7; gc.a2_ext[0] = nullptr; gc.a2_id[0] = -1;
    gc.wt_id[0] = 14; gc.bias[0] = bc1;     gc.out_id[0] = 8;
    gc.a1_id[1] = 6; gc.a2_ext[1] = nullptr; gc.a2_id[1] = -1;
    gc.wt_id[1] = 15; gc.bias[1] = nullptr; gc.out_id[1] = 9;
    gc.K1 = 128; gc.K2 = 0; gc.doRelu = 0;
    gemm_pair_kernel<<<dim3(GB, 2), 256>>>(gc);

    // 6) per-edge output
    edge_cls_kernel<<<(Et * 32 + 255) / 256, 256>>>(tei, Et, Wc2, bc2, out);
}

// round 5
// speedup vs baseline: 1.7457x; 1.4948x over previous
#include <cuda_runtime.h>
#include <cuda_bf16.h>
#include <cstdint>

// ---------------------------------------------------------------------------
// HybridGNN: 2-layer bipartite mean-SAGE + edge classifier.
// R4: GEMMs on warp-level mma.sync bf16 (portable, no sm_103a features) with
// fp32 -> bf16 hi/lo split, 3 accumulation passes. CSR pull aggregation and
// factorized edge classifier unchanged from the 682us baseline.
// ---------------------------------------------------------------------------

#define NN    50000
#define DIN   64
#define HH    128
#define EMAX  1000000
#define ETGT  500000

// ---------------- scratch ----------------
__device__ int g_stride;              // 2 if edges are int64 (int32 pairs), 1 if int32
__device__ int g_deg[2][NN];
__device__ int g_cur[2][NN];
__device__ int g_off[2][NN + 1];
__device__ int g_csr[2][EMAX];

__device__ float g_mean1_m[NN * DIN];
__device__ float g_mean1_u[NN * DIN];
__device__ float g_h_m[NN * HH];
__device__ float g_h_u[NN * HH];
__device__ float g_mean2_m[NN * HH];
__device__ float g_mean2_u[NN * HH];
__device__ float g_z_m[NN * HH];
__device__ float g_z_u[NN * HH];
__device__ float g_Pu[NN * HH];
__device__ float g_Pm[NN * HH];

__device__ __forceinline__ float* gbuf(int id) {
    switch (id) {
        case 0:  return g_mean1_m;  case 1:  return g_mean1_u;
        case 2:  return g_h_m;      case 3:  return g_h_u;
        case 4:  return g_mean2_m;  case 5:  return g_mean2_u;
        case 6:  return g_z_m;      case 7:  return g_z_u;
        case 8:  return g_Pu;       case 9:  return g_Pm;
    }
    return nullptr;
}

// ---------------- setup: zero counters + dtype detect ----------------
__global__ void setup_kernel(const int* __restrict__ e_detect) {
    int idx = blockIdx.x * blockDim.x + threadIdx.x;
    if (idx < NN) {
        g_deg[0][idx] = 0; g_deg[1][idx] = 0;
        g_cur[0][idx] = 0; g_cur[1][idx] = 0;
    }
    if (blockIdx.x == 0 && threadIdx.x < 32) {
        int lane = threadIdx.x, v = 0;
#pragma unroll
        for (int i = 0; i < 4; ++i) v |= e_detect[2 * (lane + 32 * i) + 1];
        unsigned nz = __ballot_sync(0xffffffffu, v != 0);
        if (lane == 0) g_stride = (nz == 0u) ? 2 : 1;
    }
}

// ---------------- CSR build ----------------
__global__ void count_both_kernel(const int* __restrict__ e0,
                                  const int* __restrict__ e1, int E) {
    int i = blockIdx.x * blockDim.x + threadIdx.x;
    if (i >= E) return;
    int W = blockIdx.y;
    const int* e = W ? e1 : e0;
    int st = g_stride;
    atomicAdd(&g_deg[W][e[st * (E + i)]], 1);
}

__global__ void scan_both_kernel() {
    __shared__ int s[1024];
    int W = blockIdx.x;
    int t = threadIdx.x;
    const int n = NN;
    int per = (n + 1023) / 1024;
    int start = t * per;
    int end = start + per; if (end > n) end = n; if (start > n) start = n;
    int sum = 0;
    for (int i = start; i < end; ++i) sum += g_deg[W][i];
    s[t] = sum;
    __syncthreads();
    for (int d = 1; d < 1024; d <<= 1) {
        int v = (t >= d) ? s[t - d] : 0;
        __syncthreads();
        s[t] += v;
        __syncthreads();
    }
    int run = (t == 0) ? 0 : s[t - 1];
    for (int i = start; i < end; ++i) { g_off[W][i] = run; run += g_deg[W][i]; }
    if (t == 1023) g_off[W][n] = s[1023];
}

__global__ void scatter_both_kernel(const int* __restrict__ e0,
                                    const int* __restrict__ e1, int E) {
    int i = blockIdx.x * blockDim.x + threadIdx.x;
    if (i >= E) return;
    int W = blockIdx.y;
    const int* e = W ? e1 : e0;
    int st = g_stride;
    int row = e[st * i];
    int col = e[st * (E + i)];
    int p = g_off[W][col] + atomicAdd(&g_cur[W][col], 1);
    g_csr[W][p] = row;
}

// ---------------- pull-based mean aggregation ----------------
template <int D>
__global__ void pull_pair_kernel(const float* __restrict__ x0, int x0_id, int o0,
                                 const float* __restrict__ x1, int x1_id, int o1) {
    int W = blockIdx.y;
    int w    = (blockIdx.x * blockDim.x + threadIdx.x) >> 5;
    int lane = threadIdx.x & 31;
    if (w >= NN) return;
    const float* xsrc = W ? (x1 ? x1 : gbuf(x1_id)) : (x0 ? x0 : gbuf(x0_id));
    float* mean_out = gbuf(W ? o1 : o0);
    const int* __restrict__ csr = g_csr[W];
    int s0 = g_off[W][w], s1 = g_off[W][w + 1];
    float inv = 1.0f / fmaxf((float)(s1 - s0), 1.0f);
    if (D == 128) {
        const float4* xv = (const float4*)xsrc;
        float4 acc = make_float4(0.f, 0.f, 0.f, 0.f);
        for (int j = s0; j < s1; ++j) {
            int s = csr[j];
            float4 v = __ldg(&xv[s * 32 + lane]);
            acc.x += v.x; acc.y += v.y; acc.z += v.z; acc.w += v.w;
        }
        acc.x *= inv; acc.y *= inv; acc.z *= inv; acc.w *= inv;
        ((float4*)mean_out)[w * 32 + lane] = acc;
    } else {
        const float2* xv = (const float2*)xsrc;
        float2 acc = make_float2(0.f, 0.f);
        for (int j = s0; j < s1; ++j) {
            int s = csr[j];
            float2 v = __ldg(&xv[s * 32 + lane]);
            acc.x += v.x; acc.y += v.y;
        }
        acc.x *= inv; acc.y *= inv;
        ((float2*)mean_out)[w * 32 + lane] = acc;
    }
}

// ---------------- bf16-split mma.sync paired GEMM ----------------
// out[NN x 128] = act( A @ Bt + bias ),  A fp32 [NN x Ktot], B fp32 [128 x Ktot].
// K in chunks of 32 fp32; per chunk 3 bf16 passes (hi*hi, hi*lo, lo*hi).
struct TCChunk {
    const float* a_ext;   // if null, use gbuf(a_id)
    const float* b;       // weight rows [128][ldb], K-major
    int a_id, lda, aoff, ldb, boff;
};
struct GemmTCArgs {
    TCChunk ch[2][8];
    const float* bias[2];
    int out_id[2];
    int nchunks, doRelu;
};

#define SROW 40   // bf16 elements per smem row (32 data + 8 pad) -> 80B stride

__device__ __forceinline__ uint32_t pack_bf16(float a, float b) {
    __nv_bfloat162 h = __floats2bfloat162_rn(a, b);
    return *(uint32_t*)&h;
}

__device__ __forceinline__ uint32_t smem_u32(const void* p) {
    uint32_t a;
    asm("{ .reg .u64 t; cvta.to.shared.u64 t, %1; cvt.u32.u64 %0, t; }"
        : "=r"(a) : "l"(p));
    return a;
}

__device__ __forceinline__ void ldsm4(uint32_t* r, uint32_t addr) {
    asm volatile("ldmatrix.sync.aligned.m8n8.x4.shared.b16 {%0,%1,%2,%3}, [%4];"
        : "=r"(r[0]), "=r"(r[1]), "=r"(r[2]), "=r"(r[3]) : "r"(addr));
}

__device__ __forceinline__ void mma16816(float* c, const uint32_t* a, const uint32_t* b) {
    asm volatile(
        "mma.sync.aligned.m16n8k16.row.col.f32.bf16.bf16.f32 "
        "{%0,%1,%2,%3}, {%4,%5,%6,%7}, {%8,%9}, {%0,%1,%2,%3};"
        : "+f"(c[0]), "+f"(c[1]), "+f"(c[2]), "+f"(c[3])
        : "r"(a[0]), "r"(a[1]), "r"(a[2]), "r"(a[3]), "r"(b[0]), "r"(b[1]));
}

__global__ __launch_bounds__(256)
void gemm_mma_kernel(GemmTCArgs ga) {
    __shared__ __nv_bfloat16 sAh[128 * SROW];
    __shared__ __nv_bfloat16 sAl[128 * SROW];
    __shared__ __nv_bfloat16 sBh[128 * SROW];
    __shared__ __nv_bfloat16 sBl[128 * SROW];

    const int g   = blockIdx.y;
    const int t   = threadIdx.x;
    const int wid = t >> 5, lane = t & 31;
    const int warp_m = wid & 3;        // 4 m-tiles of 32 rows
    const int warp_n = wid >> 2;       // 2 n-tiles of 64 cols
    const int r0 = blockIdx.x * 128;

    // accumulators: [mi in 0..1][n8 in 0..7][4]
    float acc[2][8][4];
#pragma unroll
    for (int i = 0; i < 2; ++i)
#pragma unroll
        for (int j = 0; j < 8; ++j) {
            acc[i][j][0] = 0.f; acc[i][j][1] = 0.f;
            acc[i][j][2] = 0.f; acc[i][j][3] = 0.f;
        }

    // staging role: each thread owns (row = t>>1, k-half = (t&1)*16)
    const int srow = t >> 1;
    const int shalf = (t & 1) * 16;
    const int rowA = r0 + srow;
    const bool validA = rowA < NN;

    // ldmatrix lane addressing (same pattern for A and B)
    const int lg = lane >> 3, lr = lane & 7;
    const int roff = (lg & 1) * 8 + lr;   // row within 16-row tile
    const int koff = (lg >> 1) * 8;       // k offset within k16

    const uint32_t bAh = smem_u32(sAh), bAl = smem_u32(sAl);
    const uint32_t bBh = smem_u32(sBh), bBl = smem_u32(sBl);

    for (int c = 0; c < ga.nchunks; ++c) {
        const TCChunk& tc = ga.ch[g][c];
        // ---- stage A row-half ----
        {
            const float* Asrc = (tc.a_ext ? tc.a_ext : gbuf(tc.a_id))
                                + (size_t)rowA * tc.lda + tc.aoff + shalf;
            uint32_t hb[8], lb[8];
#pragma unroll
            for (int j = 0; j < 4; ++j) {
                float4 v = validA ? __ldg((const float4*)(Asrc + 4 * j))
                                  : make_float4(0.f, 0.f, 0.f, 0.f);
                float hx = __bfloat162float(__float2bfloat16_rn(v.x));
                float hy = __bfloat162float(__float2bfloat16_rn(v.y));
                float hz = __bfloat162float(__float2bfloat16_rn(v.z));
                float hw = __bfloat162float(__float2bfloat16_rn(v.w));
                hb[2 * j]     = pack_bf16(v.x, v.y);
                hb[2 * j + 1] = pack_bf16(v.z, v.w);
                lb[2 * j]     = pack_bf16(v.x - hx, v.y - hy);
                lb[2 * j + 1] = pack_bf16(v.z - hz, v.w - hw);
            }
            uint32_t* ph = (uint32_t*)&sAh[srow * SROW + shalf];
            uint32_t* pl = (uint32_t*)&sAl[srow * SROW + shalf];
            *(uint4*)ph = make_uint4(hb[0], hb[1], hb[2], hb[3]);
            *(uint4*)(ph + 4) = make_uint4(hb[4], hb[5], hb[6], hb[7]);
            *(uint4*)pl = make_uint4(lb[0], lb[1], lb[2], lb[3]);
            *(uint4*)(pl + 4) = make_uint4(lb[4], lb[5], lb[6], lb[7]);
        }
        // ---- stage B row-half (weights, always valid: 128 rows) ----
        {
            const float* Bsrc = tc.b + (size_t)srow * tc.ldb + tc.boff + shalf;
            uint32_t hb[8], lb[8];
#pragma unroll
            for (int j = 0; j < 4; ++j) {
                float4 v = __ldg((const float4*)(Bsrc + 4 * j));
                float hx = __bfloat162float(__float2bfloat16_rn(v.x));
                float hy = __bfloat162float(__float2bfloat16_rn(v.y));
                float hz = __bfloat162float(__float2bfloat16_rn(v.z));
                float hw = __bfloat162float(__float2bfloat16_rn(v.w));
                hb[2 * j]     = pack_bf16(v.x, v.y);
                hb[2 * j + 1] = pack_bf16(v.z, v.w);
                lb[2 * j]     = pack_bf16(v.x - hx, v.y - hy);
                lb[2 * j + 1] = pack_bf16(v.z - hz, v.w - hw);
            }
            uint32_t* ph = (uint32_t*)&sBh[srow * SROW + shalf];
            uint32_t* pl = (uint32_t*)&sBl[srow * SROW + shalf];
            *(uint4*)ph = make_uint4(hb[0], hb[1], hb[2], hb[3]);
            *(uint4*)(ph + 4) = make_uint4(hb[4], hb[5], hb[6], hb[7]);
            *(uint4*)pl = make_uint4(lb[0], lb[1], lb[2], lb[3]);
            *(uint4*)(pl + 4) = make_uint4(lb[4], lb[5], lb[6], lb[7]);
        }
        __syncthreads();

        // ---- compute: 2 k16 steps ----
#pragma unroll
        for (int k0 = 0; k0 < 32; k0 += 16) {
            uint32_t aH[2][4], aL[2][4], bH[4][4], bL[4][4];
#pragma unroll
            for (int mi = 0; mi < 2; ++mi) {
                int m = warp_m * 32 + mi * 16 + roff;
                uint32_t off = (uint32_t)(m * SROW + k0 + koff) * 2;
                ldsm4(aH[mi], bAh + off);
                ldsm4(aL[mi], bAl + off);
            }
#pragma unroll
            for (int ni = 0; ni < 4; ++ni) {
                int nrow = warp_n * 64 + ni * 16 + roff;
                uint32_t off = (uint32_t)(nrow * SROW + k0 + koff) * 2;
                ldsm4(bH[ni], bBh + off);
                ldsm4(bL[ni], bBl + off);
            }
#pragma unroll
            for (int mi = 0; mi < 2; ++mi)
#pragma unroll
                for (int ni = 0; ni < 4; ++ni)
#pragma unroll
                    for (int sub = 0; sub < 2; ++sub) {
                        uint32_t b0h[2] = {bH[ni][sub], bH[ni][2 + sub]};
                        uint32_t b0l[2] = {bL[ni][sub], bL[ni][2 + sub]};
                        float* cc = acc[mi][ni * 2 + sub];
                        mma16816(cc, aH[mi], b0h);   // hi*hi
                        mma16816(cc, aH[mi], b0l);   // hi*lo
                        mma16816(cc, aL[mi], b0h);   // lo*hi
                    }
        }
        __syncthreads();
    }

    // ---- epilogue ----
    const float* bias = ga.bias[g];
    float* out = gbuf(ga.out_id[g]);
    const int tg = lane >> 2, tid4 = lane & 3;
#pragma unroll
    for (int j = 0; j < 8; ++j) {
        int col = warp_n * 64 + j * 8 + tid4 * 2;
        float2 bb = bias ? *(const float2*)&bias[col] : make_float2(0.f, 0.f);
#pragma unroll
        for (int mi = 0; mi < 2; ++mi) {
            int row0 = r0 + warp_m * 32 + mi * 16 + tg;
            float* cc = acc[mi][j];
            float2 v0 = make_float2(cc[0] + bb.x, cc[1] + bb.y);
            float2 v1 = make_float2(cc[2] + bb.x, cc[3] + bb.y);
            if (ga.doRelu) {
                v0.x = fmaxf(v0.x, 0.f); v0.y = fmaxf(v0.y, 0.f);
                v1.x = fmaxf(v1.x, 0.f); v1.y = fmaxf(v1.y, 0.f);
            }
            if (row0 < NN)     *(float2*)&out[(size_t)row0 * 128 + col] = v0;
            if (row0 + 8 < NN) *(float2*)&out[(size_t)(row0 + 8) * 128 + col] = v1;
        }
    }
}

// ---------------- edge classifier ----------------
__global__ void edge_cls_kernel(const int* __restrict__ tei, int Et,
                                const float* __restrict__ Wc2,
                                const float* __restrict__ bc2,
                                float* __restrict__ out) {
    int w    = (blockIdx.x * blockDim.x + threadIdx.x) >> 5;
    int lane = threadIdx.x & 31;
    if (w >= Et) return;
    int st = g_stride;
    int ru = tei[st * w];
    int rm = tei[st * (Et + w)];
    float4 u  = __ldg(&((const float4*)g_Pu)[ru * 32 + lane]);
    float4 m  = __ldg(&((const float4*)g_Pm)[rm * 32 + lane]);
    float4 wv = __ldg(&((const float4*)Wc2)[lane]);
    float a = fmaxf(u.x + m.x, 0.f) * wv.x
            + fmaxf(u.y + m.y, 0.f) * wv.y
            + fmaxf(u.z + m.z, 0.f) * wv.z
            + fmaxf(u.w + m.w, 0.f) * wv.w;
#pragma unroll
    for (int o = 16; o; o >>= 1) a += __shfl_xor_sync(0xffffffffu, a, o);
    if (lane == 0) out[w] = a + bc2[0];
}

// ---------------- host launcher ----------------
extern "C" void kernel_launch(void* const* d_in, const int* in_sizes, int n_in,
                              void* d_out, int out_size) {
    const float* x_user  = (const float*)d_in[0];
    const float* x_merch = (const float*)d_in[1];
    const int*   e_um    = (const int*)d_in[2];
    const int*   e_mu    = (const int*)d_in[3];
    const int*   tei     = (const int*)d_in[4];
    const float* W1_um_l = (const float*)d_in[5];
    const float* b1_um_l = (const float*)d_in[6];
    const float* W1_um_r = (const float*)d_in[7];
    const float* W1_mu_l = (const float*)d_in[8];
    const float* b1_mu_l = (const float*)d_in[9];
    const float* W1_mu_r = (const float*)d_in[10];
    const float* W2_um_l = (const float*)d_in[11];
    const float* b2_um_l = (const float*)d_in[12];
    const float* W2_um_r = (const float*)d_in[13];
    const float* W2_mu_l = (const float*)d_in[14];
    const float* b2_mu_l = (const float*)d_in[15];
    const float* W2_mu_r = (const float*)d_in[16];
    const float* Wc1     = (const float*)d_in[17];
    const float* bc1     = (const float*)d_in[18];
    const float* Wc2     = (const float*)d_in[19];
    const float* bc2     = (const float*)d_in[20];

    const int E  = EMAX;
    const int Et = ETGT;
    float* out = (float*)d_out;

    // 1) setup
    setup_kernel<<<(NN + 255) / 256, 256>>>(e_um);

    // 2) CSR build
    const int EB = (E + 255) / 256;
    count_both_kernel<<<dim3(EB, 2), 256>>>(e_um, e_mu, E);
    scan_both_kernel<<<2, 1024>>>();
    scatter_both_kernel<<<dim3(EB, 2), 256>>>(e_um, e_mu, E);

    const int PB = (NN * 32 + 255) / 256;
    const int GB = (NN + 127) / 128;

    auto CH = [](const float* a_ext, int a_id, int lda, int aoff,
                 const float* b, int ldb, int boff) {
        TCChunk c; c.a_ext = a_ext; c.a_id = a_id; c.lda = lda; c.aoff = aoff;
        c.b = b; c.ldb = ldb; c.boff = boff; return c;
    };

    // 3) layer 1 (relu)
    pull_pair_kernel<64><<<dim3(PB, 2), 256>>>(x_user, -1, 0, x_merch, -1, 1);
    GemmTCArgs g1;
    g1.ch[0][0] = CH(nullptr, 0, 64, 0,  W1_um_l, 64, 0);
    g1.ch[0][1] = CH(nullptr, 0, 64, 32, W1_um_l, 64, 32);
    g1.ch[0][2] = CH(x_merch, -1, 64, 0,  W1_um_r, 64, 0);
    g1.ch[0][3] = CH(x_merch, -1, 64, 32, W1_um_r, 64, 32);
    g1.ch[1][0] = CH(nullptr, 1, 64, 0,  W1_mu_l, 64, 0);
    g1.ch[1][1] = CH(nullptr, 1, 64, 32, W1_mu_l, 64, 32);
    g1.ch[1][2] = CH(x_user, -1, 64, 0,  W1_mu_r, 64, 0);
    g1.ch[1][3] = CH(x_user, -1, 64, 32, W1_mu_r, 64, 32);
    g1.bias[0] = b1_um_l; g1.bias[1] = b1_mu_l;
    g1.out_id[0] = 2; g1.out_id[1] = 3;
    g1.nchunks = 4; g1.doRelu = 1;
    gemm_mma_kernel<<<dim3(GB, 2), 256>>>(g1);

    // 4) layer 2 (no relu)
    pull_pair_kernel<128><<<dim3(PB, 2), 256>>>(nullptr, 3, 4, nullptr, 2, 5);
    GemmTCArgs g2;
    for (int q = 0; q < 4; ++q) {
        g2.ch[0][q]     = CH(nullptr, 4, 128, 32 * q, W2_um_l, 128, 32 * q);
        g2.ch[0][4 + q] = CH(nullptr, 2, 128, 32 * q, W2_um_r, 128, 32 * q);
        g2.ch[1][q]     = CH(nullptr, 5, 128, 32 * q, W2_mu_l, 128, 32 * q);
        g2.ch[1][4 + q] = CH(nullptr, 3, 128, 32 * q, W2_mu_r, 128, 32 * q);
    }
    g2.bias[0] = b2_um_l; g2.bias[1] = b2_mu_l;
    g2.out_id[0] = 6; g2.out_id[1] = 7;
    g2.nchunks = 8; g2.doRelu = 0;
    gemm_mma_kernel<<<dim3(GB, 2), 256>>>(g2);

    // 5) classifier projections (bc1 folded into Pu)
    GemmTCArgs gc;
    for (int q = 0; q < 4; ++q) {
        gc.ch[0][q] = CH(nullptr, 7, 128, 32 * q, Wc1, 256, 32 * q);        // user half
        gc.ch[1][q] = CH(nullptr, 6, 128, 32 * q, Wc1, 256, 128 + 32 * q);  // merchant half
    }
    gc.bias[0] = bc1; gc.bias[1] = nullptr;
    gc.out_id[0] = 8; gc.out_id[1] = 9;
    gc.nchunks = 4; gc.doRelu = 0;
    gemm_mma_kernel<<<dim3(GB, 2), 256>>>(gc);

    // 6) per-edge output
    edge_cls_kernel<<<(Et * 32 + 255) / 256, 256>>>(tei, Et, Wc2, bc2, out);
}